// round 3
// baseline (speedup 1.0000x reference)
#include <cuda_runtime.h>

#define NJ   32
#define TPB  128
#define EPB  (TPB * 2)     // elements per block (2 per thread)
#define OUTC 94

// ---- dynamic smem float offsets ----
#define S_OUT   0
#define S_TGT   (TPB * OUTC)          // 12032  (4 x 7)
#define S_DB    (S_TGT + 28)          //        (7)
#define S_REST  (S_DB + 7)            //        (32)
#define S_JLO   (S_REST + 32)         //        (32)
#define S_JUP   (S_JLO + 32)          //        (32)
#define S_JOFF  (S_JUP + 32)          //        (32 x 7)
#define S_P     (S_JOFF + 224)        //        (32 x 4)
#define S_TOTAL (S_P + 128)           // 12515 floats = 50060 B

struct Q { float x, y, z, w; };
struct V { float x, y, z; };

__device__ __forceinline__ V vcross(V a, V b) {
    return {a.y * b.z - a.z * b.y,
            a.z * b.x - a.x * b.z,
            a.x * b.y - a.y * b.x};
}

// t + 2*(v x (v x t + w t))
__device__ __forceinline__ V qrot(Q q, V t) {
    V v{q.x, q.y, q.z};
    V u = vcross(v, t);
    u.x = fmaf(q.w, t.x, u.x);
    u.y = fmaf(q.w, t.y, u.y);
    u.z = fmaf(q.w, t.z, u.z);
    V c = vcross(v, u);
    return {fmaf(2.0f, c.x, t.x), fmaf(2.0f, c.y, t.y), fmaf(2.0f, c.z, t.z)};
}

__device__ __forceinline__ Q qmul(Q a, Q b) {
    Q r;
    r.w = a.w * b.w - a.x * b.x - a.y * b.y - a.z * b.z;
    r.x = a.w * b.x + b.w * a.x + a.y * b.z - a.z * b.y;
    r.y = a.w * b.y + b.w * a.y + a.z * b.x - a.x * b.z;
    r.z = a.w * b.z + b.w * a.z + a.x * b.y - a.y * b.x;
    return r;
}

// atan2(y, x) for y >= 0, x >= 0, not both zero. 6-coeff minimax atan on [0,1].
__device__ __forceinline__ float atan2pos(float y, float x) {
    float mn = fminf(y, x), mx = fmaxf(y, x);
    float r  = __fdividef(mn, mx);
    float r2 = r * r;
    float p = fmaf(r2, -0.0117212f,  0.05265332f);
    p = fmaf(r2, p, -0.11643287f);
    p = fmaf(r2, p,  0.19354346f);
    p = fmaf(r2, p, -0.33262347f);
    p = fmaf(r2, p,  0.99997726f);
    float th = r * p;
    return (y > x) ? (1.57079632679489662f - th) : th;
}

// se3_log for UNIT quaternion (trig-free: |phi| == angle for unit q)
__device__ __forceinline__ void se3_log(V t, Q q, V& rho, V& phi) {
    float sgn = (q.w < 0.0f) ? -1.0f : 1.0f;
    float qx = q.x * sgn, qy = q.y * sgn, qz = q.z * sgn, qw = q.w * sgn;
    float nv2 = qx * qx + qy * qy + qz * qz;
    float nv  = sqrtf(fmaxf(nv2, 1e-14f));
    float angle = 2.0f * atan2pos(nv, qw);
    float wsafe = (fabsf(qw) > 1e-8f) ? qw : 1.0f;
    float scale = (nv < 1e-6f) ? __fdividef(2.0f, wsafe) : __fdividef(angle, nv);
    phi = {qx * scale, qy * scale, qz * scale};

    float th  = angle;
    float th2 = th * th;
    float abig = __fdividef(1.0f - 0.5f * scale * qw, th2);
    float a = (th < 1e-4f) ? (1.0f / 12.0f + th2 * (1.0f / 720.0f)) : abig;

    V pt  = vcross(phi, t);
    V ppt = vcross(phi, pt);
    rho = {t.x - 0.5f * pt.x + a * ppt.x,
           t.y - 0.5f * pt.y + a * ppt.y,
           t.z - 0.5f * pt.z + a * ppt.z};
}

// log( inv(target) o actual ), target pose (7 floats) from smem
__device__ __forceinline__ void pose_err_log(const float* tp, V at, Q aq,
                                             V& rho, V& phi) {
    Q qi{-tp[3], -tp[4], -tp[5], tp[6]};
    V d{at.x - tp[0], at.y - tp[1], at.z - tp[2]};
    V pe = qrot(qi, d);
    Q qe = qmul(qi, aq);
    se3_log(pe, qe, rho, phi);
}

// one FK chain step (constants from smem; uniform across warp -> LDS broadcast)
__device__ __forceinline__ void fk_step(const float* s, int j, float thj,
                                        V& Tt, Q& Tq) {
    const float* o = s + S_JOFF + j * 7;
    V ot{o[0], o[1], o[2]};
    Q oq{o[3], o[4], o[5], o[6]};
    V rt = qrot(Tq, ot);
    Tt.x += rt.x; Tt.y += rt.y; Tt.z += rt.z;

    float sh, ch;
    __sincosf(0.5f * thj, &sh, &ch);
    const float* pj = s + S_P + j * 4;
    Q M{ch * oq.x + sh * pj[0],
        ch * oq.y + sh * pj[1],
        ch * oq.z + sh * pj[2],
        ch * oq.w + sh * pj[3]};
    Tq = qmul(Tq, M);
}

__global__ void __launch_bounds__(TPB, 2)
ik_residual_kernel(const float* __restrict__ cfg,
                   const float* __restrict__ base,
                   const float* __restrict__ tgt,
                   const float* __restrict__ dbase,
                   const float* __restrict__ rest,
                   const float* __restrict__ joff,
                   const float* __restrict__ jaxis,
                   const float* __restrict__ jlo,
                   const float* __restrict__ jup,
                   float* __restrict__ out) {
    extern __shared__ float s[];

    const int t  = threadIdx.x;
    const int e0 = blockIdx.x * EPB;

    // ---- stage constants + both base-pose tiles (base tile -> S_OUT scratch) ----
    {
        const float* gb = base + (size_t)e0 * 7;
        #pragma unroll
        for (int i = t; i < EPB * 7; i += TPB) s[S_OUT + i] = gb[i];
        #pragma unroll
        for (int i = t; i < 224; i += TPB) s[S_JOFF + i] = __ldg(joff + i);
        if (t < 28) s[S_TGT + t] = __ldg(tgt + t);
        if (t < 7)  s[S_DB + t]  = __ldg(dbase + t);
        if (t < 32) {
            s[S_REST + t] = __ldg(rest + t);
            s[S_JLO + t]  = __ldg(jlo + t);
            s[S_JUP + t]  = __ldg(jup + t);
            // P_j = oq_j (x) [axis_j, 0]
            float ox = __ldg(joff + t * 7 + 3), oy = __ldg(joff + t * 7 + 4);
            float oz = __ldg(joff + t * 7 + 5), ow = __ldg(joff + t * 7 + 6);
            float ax = __ldg(jaxis + t * 3 + 0), ay = __ldg(jaxis + t * 3 + 1);
            float az = __ldg(jaxis + t * 3 + 2);
            s[S_P + t * 4 + 0] = ow * ax + oy * az - oz * ay;
            s[S_P + t * 4 + 1] = ow * ay + oz * ax - ox * az;
            s[S_P + t * 4 + 2] = ow * az + ox * ay - oy * ax;
            s[S_P + t * 4 + 3] = -(ox * ax + oy * ay + oz * az);
        }
    }
    __syncthreads();

    V TtA{s[S_OUT + t * 7 + 0], s[S_OUT + t * 7 + 1], s[S_OUT + t * 7 + 2]};
    Q TqA{s[S_OUT + t * 7 + 3], s[S_OUT + t * 7 + 4], s[S_OUT + t * 7 + 5], s[S_OUT + t * 7 + 6]};
    V TtB{s[S_OUT + (TPB + t) * 7 + 0], s[S_OUT + (TPB + t) * 7 + 1], s[S_OUT + (TPB + t) * 7 + 2]};
    Q TqB{s[S_OUT + (TPB + t) * 7 + 3], s[S_OUT + (TPB + t) * 7 + 4], s[S_OUT + (TPB + t) * 7 + 5], s[S_OUT + (TPB + t) * 7 + 6]};
    V bposA{TtA.x, TtA.y, TtA.z};  Q bqA = TqA;
    V bposB{TtB.x, TtB.y, TtB.z};  Q bqB = TqB;
    __syncthreads();   // base scratch region becomes the output buffer

    // ---- load both cfg rows ----
    float thA[NJ], thB[NJ];
    {
        const float4* cA = (const float4*)(cfg + (size_t)(e0 + t) * NJ);
        const float4* cB = (const float4*)(cfg + (size_t)(e0 + TPB + t) * NJ);
        #pragma unroll
        for (int i = 0; i < NJ / 4; i++) {
            float4 a = __ldg(cA + i);
            thA[4*i+0] = a.x; thA[4*i+1] = a.y; thA[4*i+2] = a.z; thA[4*i+3] = a.w;
            float4 b = __ldg(cB + i);
            thB[4*i+0] = b.x; thB[4*i+1] = b.y; thB[4*i+2] = b.z; thB[4*i+3] = b.w;
        }
    }

    float* row = s + S_OUT + t * OUTC;
    float bres[30];   // B pose (24) + B base (6) residuals, held in regs

    // ---- two interleaved FK chains ----
    #pragma unroll
    for (int j = 0; j < NJ; j++) {
        // A limit/rest -> smem row
        float limA = fmaxf(thA[j] - s[S_JUP + j], 0.0f) + fminf(thA[j] - s[S_JLO + j], 0.0f);
        row[24 + j] = limA * 10.0f;
        row[56 + j] = (thA[j] - s[S_REST + j]) * 0.1f;

        fk_step(s, j, thA[j], TtA, TqA);
        fk_step(s, j, thB[j], TtB, TqB);

        if ((j & 7) == 7) {   // TARGET_LINKS = 8,16,24,32
            int k = j >> 3;
            V rho, phi;
            pose_err_log(s + S_TGT + k * 7, TtA, TqA, rho, phi);
            row[k * 6 + 0] = rho.x;
            row[k * 6 + 1] = rho.y;
            row[k * 6 + 2] = rho.z;
            row[k * 6 + 3] = 0.5f * phi.x;
            row[k * 6 + 4] = 0.5f * phi.y;
            row[k * 6 + 5] = 0.5f * phi.z;
            pose_err_log(s + S_TGT + k * 7, TtB, TqB, rho, phi);
            bres[k * 6 + 0] = rho.x;
            bres[k * 6 + 1] = rho.y;
            bres[k * 6 + 2] = rho.z;
            bres[k * 6 + 3] = 0.5f * phi.x;
            bres[k * 6 + 4] = 0.5f * phi.y;
            bres[k * 6 + 5] = 0.5f * phi.z;
        }
    }

    // ---- base residuals ----
    {
        V rho, phi;
        pose_err_log(s + S_DB, bposA, bqA, rho, phi);
        row[88] = rho.x * 5.0f; row[89] = rho.y * 5.0f; row[90] = rho.z * 5.0f;
        row[91] = phi.x * 5.0f; row[92] = phi.y * 5.0f; row[93] = phi.z * 5.0f;
        pose_err_log(s + S_DB, bposB, bqB, rho, phi);
        bres[24] = rho.x * 5.0f; bres[25] = rho.y * 5.0f; bres[26] = rho.z * 5.0f;
        bres[27] = phi.x * 5.0f; bres[28] = phi.y * 5.0f; bres[29] = phi.z * 5.0f;
    }

    __syncthreads();

    // ---- flush phase 1: elements [e0, e0+128) ----
    {
        float4* go4 = (float4*)(out + (size_t)e0 * OUTC);
        const float4* s4 = (const float4*)(s + S_OUT);
        for (int f = t; f < TPB * OUTC / 4; f += TPB) go4[f] = s4[f];
    }
    __syncthreads();

    // ---- phase 2: write B residuals into the (now free) buffer ----
    #pragma unroll
    for (int i = 0; i < 24; i++) row[i] = bres[i];
    #pragma unroll
    for (int j = 0; j < NJ; j++) {
        float limB = fmaxf(thB[j] - s[S_JUP + j], 0.0f) + fminf(thB[j] - s[S_JLO + j], 0.0f);
        row[24 + j] = limB * 10.0f;
        row[56 + j] = (thB[j] - s[S_REST + j]) * 0.1f;
    }
    #pragma unroll
    for (int i = 0; i < 6; i++) row[88 + i] = bres[24 + i];

    __syncthreads();

    // ---- flush phase 2: elements [e0+128, e0+256) ----
    {
        float4* go4 = (float4*)(out + (size_t)(e0 + TPB) * OUTC);
        const float4* s4 = (const float4*)(s + S_OUT);
        for (int f = t; f < TPB * OUTC / 4; f += TPB) go4[f] = s4[f];
    }
}

extern "C" void kernel_launch(void* const* d_in, const int* in_sizes, int n_in,
                              void* d_out, int out_size) {
    const float* cfg   = (const float*)d_in[0];
    const float* base  = (const float*)d_in[1];
    const float* tgt   = (const float*)d_in[2];
    const float* dbase = (const float*)d_in[3];
    const float* rest  = (const float*)d_in[4];
    const float* joff  = (const float*)d_in[5];
    const float* jaxis = (const float*)d_in[6];
    const float* jlo   = (const float*)d_in[7];
    const float* jup   = (const float*)d_in[8];
    float* out = (float*)d_out;

    const int smem_bytes = S_TOTAL * sizeof(float);   // 50060
    cudaFuncSetAttribute(ik_residual_kernel,
                         cudaFuncAttributeMaxDynamicSharedMemorySize, smem_bytes);

    int B = in_sizes[0] / NJ;     // 65536
    int nblocks = B / EPB;        // 256

    ik_residual_kernel<<<nblocks, TPB, smem_bytes>>>(cfg, base, tgt, dbase, rest,
                                                     joff, jaxis, jlo, jup, out);
}